// round 5
// baseline (speedup 1.0000x reference)
#include <cuda_runtime.h>
#include <cuda_bf16.h>
#include <cstdint>

#define BB 2
#define NN 4096
#define HH 256
#define NHEADS 4
#define DH 64
#define MTOT (BB*NN)                 // 8192 rows
#define PLANE ((size_t)MTOT * HH)    // elements per hi/lo plane (2M)
#define EPLANE ((size_t)8 * NN * NN) // elements per E plane (128M)

// ---------------------------------------------------------------------------
// Scratch (__device__ globals — no cudaMalloc allowed)
// ---------------------------------------------------------------------------
__device__ float g_Q [(size_t)MTOT * HH];
__device__ float g_K [(size_t)MTOT * HH];
__device__ float g_V [(size_t)MTOT * HH];
__device__ float g_AV[(size_t)MTOT * HH];
__device__ float g_S [134217728ULL];                 // 512 MB masked scores
__device__ __nv_bfloat16 g_Qbf[2 * PLANE];           // hi | lo
__device__ __nv_bfloat16 g_Kbf[2 * PLANE];
__device__ __nv_bfloat16 g_Vbf[2 * PLANE];
__device__ __nv_bfloat16 g_Ebf[2 * EPLANE];          // exp(s-m) hi | lo (512 MB)
__device__ float g_il[8 * NN];                       // 1/l per (bh, i)

#define NEG_INF __int_as_float(0xff800000)

// ---------------------------------------------------------------------------
// helpers
// ---------------------------------------------------------------------------
__device__ __forceinline__ uint32_t smem_u32(const void* p) {
    return (uint32_t)__cvta_generic_to_shared(p);
}
__device__ __forceinline__ void split_bf16(float x, __nv_bfloat16& h, __nv_bfloat16& l) {
    h = __float2bfloat16_rn(x);
    l = __float2bfloat16_rn(x - __bfloat162float(h));
}
__device__ __forceinline__ void ldsm_x4(uint32_t addr, uint32_t& r0, uint32_t& r1,
                                        uint32_t& r2, uint32_t& r3) {
    asm volatile("ldmatrix.sync.aligned.m8n8.x4.shared.b16 {%0,%1,%2,%3}, [%4];"
                 : "=r"(r0), "=r"(r1), "=r"(r2), "=r"(r3) : "r"(addr));
}
__device__ __forceinline__ void ldsm_x4_t(uint32_t addr, uint32_t& r0, uint32_t& r1,
                                          uint32_t& r2, uint32_t& r3) {
    asm volatile("ldmatrix.sync.aligned.m8n8.x4.trans.shared.b16 {%0,%1,%2,%3}, [%4];"
                 : "=r"(r0), "=r"(r1), "=r"(r2), "=r"(r3) : "r"(addr));
}
__device__ __forceinline__ void mma_bf16(float* d, const uint32_t* a, const uint32_t* b) {
    asm volatile(
        "mma.sync.aligned.m16n8k16.row.col.f32.bf16.bf16.f32 "
        "{%0,%1,%2,%3}, {%4,%5,%6,%7}, {%8,%9}, {%0,%1,%2,%3};"
        : "+f"(d[0]), "+f"(d[1]), "+f"(d[2]), "+f"(d[3])
        : "r"(a[0]), "r"(a[1]), "r"(a[2]), "r"(a[3]), "r"(b[0]), "r"(b[1]));
}

// ---------------------------------------------------------------------------
// GEMM (fp32): Y[m,o] = sum_k X[m,k] * W[o,k] + bias[o]
// ---------------------------------------------------------------------------
__global__ __launch_bounds__(256) void gemm_xwt(
    const float* __restrict__ X, const float* __restrict__ W,
    const float* __restrict__ bias, float* __restrict__ Y)
{
    __shared__ float Xs[64 * 65];
    __shared__ float Ws[64 * 65];
    const int tid = threadIdx.x;
    const int tx = tid & 15, ty = tid >> 4;
    const int m0 = blockIdx.x * 64, n0 = blockIdx.y * 64;

    float acc[4][4] = {};

    for (int k0 = 0; k0 < HH; k0 += 64) {
        __syncthreads();
        #pragma unroll
        for (int it = 0; it < 4; it++) {
            int f   = tid + it * 256;
            int row = f >> 4;
            int dq  = f & 15;
            float4 xv = *(const float4*)&X[(size_t)(m0 + row) * HH + k0 + dq * 4];
            Xs[row * 65 + dq * 4 + 0] = xv.x;
            Xs[row * 65 + dq * 4 + 1] = xv.y;
            Xs[row * 65 + dq * 4 + 2] = xv.z;
            Xs[row * 65 + dq * 4 + 3] = xv.w;
            float4 wv = *(const float4*)&W[(size_t)(n0 + row) * HH + k0 + dq * 4];
            Ws[row * 65 + dq * 4 + 0] = wv.x;
            Ws[row * 65 + dq * 4 + 1] = wv.y;
            Ws[row * 65 + dq * 4 + 2] = wv.z;
            Ws[row * 65 + dq * 4 + 3] = wv.w;
        }
        __syncthreads();
        #pragma unroll 8
        for (int k = 0; k < 64; k++) {
            float a[4], b[4];
            #pragma unroll
            for (int ii = 0; ii < 4; ii++) a[ii] = Xs[(ty * 4 + ii) * 65 + k];
            #pragma unroll
            for (int jj = 0; jj < 4; jj++) b[jj] = Ws[(tx * 4 + jj) * 65 + k];
            #pragma unroll
            for (int ii = 0; ii < 4; ii++)
                #pragma unroll
                for (int jj = 0; jj < 4; jj++)
                    acc[ii][jj] = fmaf(a[ii], b[jj], acc[ii][jj]);
        }
    }

    float4 bv = *(const float4*)&bias[n0 + tx * 4];
    #pragma unroll
    for (int ii = 0; ii < 4; ii++) {
        float4 o;
        o.x = acc[ii][0] + bv.x;
        o.y = acc[ii][1] + bv.y;
        o.z = acc[ii][2] + bv.z;
        o.w = acc[ii][3] + bv.w;
        *(float4*)&Y[(size_t)(m0 + ty * 4 + ii) * HH + n0 + tx * 4] = o;
    }
}

// ---------------------------------------------------------------------------
// Convert Q,K,V fp32 -> bf16 hi/lo planes. grid (2048, 3), 256 thr.
// ---------------------------------------------------------------------------
__global__ __launch_bounds__(256) void convert_qkv_kernel()
{
    const size_t idx = (size_t)blockIdx.x * 256 + threadIdx.x;   // float4 index
    const float* src = (blockIdx.y == 0) ? g_Q : (blockIdx.y == 1) ? g_K : g_V;
    __nv_bfloat16* dst = (blockIdx.y == 0) ? g_Qbf : (blockIdx.y == 1) ? g_Kbf : g_Vbf;
    float4 v = ((const float4*)src)[idx];
    __nv_bfloat16 hi[4], lo[4];
    split_bf16(v.x, hi[0], lo[0]);
    split_bf16(v.y, hi[1], lo[1]);
    split_bf16(v.z, hi[2], lo[2]);
    split_bf16(v.w, hi[3], lo[3]);
    ((uint2*)dst)[idx]           = *(uint2*)hi;
    ((uint2*)(dst + PLANE))[idx] = *(uint2*)lo;
}

// ---------------------------------------------------------------------------
// Scores (mma.sync): tile 128x128, k=64, 3-pass hi/lo; fills from bf16 planes.
// grid: x=bh(8), y=jt(32), z=it(32); 256 threads
// ---------------------------------------------------------------------------
#define LDQ 136   // bf16 stride: 64 hi | 64 lo | 8 pad

__global__ __launch_bounds__(256) void scores_mma(
    const float* __restrict__ tau, const int* __restrict__ adj,
    const float* __restrict__ cw, const float* __restrict__ cb)
{
    extern __shared__ __nv_bfloat16 sm[];
    __nv_bfloat16* Qs = sm;                 // [128][LDQ]
    __nv_bfloat16* Ks = sm + 128 * LDQ;     // [128][LDQ]

    const int tid  = threadIdx.x;
    const int lane = tid & 31, warp = tid >> 5;
    const int wm = warp >> 2, wn = warp & 3;      // 2 x 4 warp grid
    const int bh = blockIdx.x;
    const int b = bh >> 2, h = bh & 3;
    const int j0 = blockIdx.y * 128, i0 = blockIdx.z * 128;

    const size_t qoff = (size_t)(b * NN + i0) * HH + h * DH;
    const size_t koff = (size_t)(b * NN + j0) * HH + h * DH;

    // fill: 4096 uint4 chunks: mat(2) x plane(2) x row(128) x c(8)
    #pragma unroll
    for (int it = 0; it < 16; it++) {
        int f = tid + it * 256;
        int mat = f >> 11;
        int p   = (f >> 10) & 1;
        int r   = (f >> 3) & 127;
        int c   = f & 7;
        const __nv_bfloat16* src = (mat ? g_Kbf : g_Qbf) + (size_t)p * PLANE
                                 + (mat ? koff : qoff) + (size_t)r * HH + c * 8;
        __nv_bfloat16* dst = (mat ? Ks : Qs) + r * LDQ + p * 64 + c * 8;
        *(uint4*)dst = *(const uint4*)src;
    }
    __syncthreads();

    float acc[4][4][4] = {};
    const uint32_t qbase = smem_u32(Qs);
    const uint32_t kbase = smem_u32(Ks);

    #pragma unroll
    for (int pass = 0; pass < 3; pass++) {
        const int aOff = (pass == 1) ? 64 : 0;
        const int bOff = (pass == 2) ? 64 : 0;
        #pragma unroll
        for (int ks = 0; ks < 4; ks++) {
            const int kc = ks * 16;
            uint32_t a[4][4];
            #pragma unroll
            for (int mt = 0; mt < 4; mt++) {
                int r = wm * 64 + mt * 16 + (lane & 15);
                int c = aOff + kc + ((lane >> 4) << 3);
                ldsm_x4(qbase + (uint32_t)(r * LDQ + c) * 2,
                        a[mt][0], a[mt][1], a[mt][2], a[mt][3]);
            }
            uint32_t bf[4][2];
            #pragma unroll
            for (int hf = 0; hf < 2; hf++) {
                int r = wn * 32 + hf * 16 + ((lane >> 4) << 3) + (lane & 7);
                int c = bOff + kc + (lane & 8);
                uint32_t r0, r1, r2, r3;
                ldsm_x4(kbase + (uint32_t)(r * LDQ + c) * 2, r0, r1, r2, r3);
                bf[hf * 2 + 0][0] = r0; bf[hf * 2 + 0][1] = r1;
                bf[hf * 2 + 1][0] = r2; bf[hf * 2 + 1][1] = r3;
            }
            #pragma unroll
            for (int mt = 0; mt < 4; mt++)
                #pragma unroll
                for (int nt = 0; nt < 4; nt++)
                    mma_bf16(acc[mt][nt], a[mt], bf[nt]);
        }
    }

    // epilogue: scale, credibility bias, adjacency mask, store
    const float cwh = cw[h], cbh = cb[h];
    const float* taub = tau + (size_t)b * NN;
    const int g  = lane >> 2;
    const int t2 = (lane & 3) * 2;

    float2 tj[4];
    #pragma unroll
    for (int nt = 0; nt < 4; nt++)
        tj[nt] = *(const float2*)&taub[j0 + wn * 32 + nt * 8 + t2];

    #pragma unroll
    for (int mt = 0; mt < 4; mt++) {
        const int r0 = i0 + wm * 64 + mt * 16 + g;
        const int r1 = r0 + 8;
        const float ti0 = taub[r0], ti1 = taub[r1];
        #pragma unroll
        for (int nt = 0; nt < 4; nt++) {
            const int col = j0 + wn * 32 + nt * 8 + t2;
            int2 a0 = *(const int2*)&adj[(size_t)r0 * NN + col];
            int2 a1 = *(const int2*)&adj[(size_t)r1 * NN + col];
            float* ac = acc[mt][nt];
            float2 o0, o1;
            o0.x = a0.x ? fmaf(ac[0], 0.125f, fmaf(ti0 * tj[nt].x, cwh, cbh)) : NEG_INF;
            o0.y = a0.y ? fmaf(ac[1], 0.125f, fmaf(ti0 * tj[nt].y, cwh, cbh)) : NEG_INF;
            o1.x = a1.x ? fmaf(ac[2], 0.125f, fmaf(ti1 * tj[nt].x, cwh, cbh)) : NEG_INF;
            o1.y = a1.y ? fmaf(ac[3], 0.125f, fmaf(ti1 * tj[nt].y, cwh, cbh)) : NEG_INF;
            *(float2*)&g_S[((size_t)bh * NN + r0) * NN + col] = o0;
            *(float2*)&g_S[((size_t)bh * NN + r1) * NN + col] = o1;
        }
    }
}

// ---------------------------------------------------------------------------
// Softmax stats + head-mean: reads S, writes E=exp(s-m) bf16 hi/lo planes,
// inv_l per row, and attn-mean. No fp32 P write-back.
// ---------------------------------------------------------------------------
__device__ __forceinline__ float warpMax(float v) {
    #pragma unroll
    for (int o = 16; o > 0; o >>= 1) v = fmaxf(v, __shfl_xor_sync(0xffffffffu, v, o));
    return v;
}
__device__ __forceinline__ float warpSum(float v) {
    #pragma unroll
    for (int o = 16; o > 0; o >>= 1) v += __shfl_xor_sync(0xffffffffu, v, o);
    return v;
}

__global__ __launch_bounds__(256) void softmax_kernel(float* __restrict__ out_am)
{
    const int bi = blockIdx.x;
    const int b = bi >> 12, i = bi & 4095;
    const int tid = threadIdx.x;
    const int lane = tid & 31, wid = tid >> 5;
    __shared__ float red[8];

    float macc[16];
    #pragma unroll
    for (int r = 0; r < 16; r++) macc[r] = 0.f;

    for (int h = 0; h < NHEADS; h++) {
        const int bh = b * 4 + h;
        const float* row = g_S + ((size_t)bh * NN + i) * NN;
        float p[16];
        #pragma unroll
        for (int r = 0; r < 4; r++) {
            float4 v = *(const float4*)&row[(tid + r * 256) * 4];
            p[r * 4 + 0] = v.x; p[r * 4 + 1] = v.y;
            p[r * 4 + 2] = v.z; p[r * 4 + 3] = v.w;
        }
        float m = p[0];
        #pragma unroll
        for (int r = 1; r < 16; r++) m = fmaxf(m, p[r]);
        m = warpMax(m);
        if (lane == 0) red[wid] = m;
        __syncthreads();
        if (wid == 0) {
            float x = (lane < 8) ? red[lane] : NEG_INF;
            x = warpMax(x);
            if (lane == 0) red[0] = x;
        }
        __syncthreads();
        m = red[0];
        __syncthreads();
        float s = 0.f;
        #pragma unroll
        for (int r = 0; r < 16; r++) { p[r] = __expf(p[r] - m); s += p[r]; }
        s = warpSum(s);
        if (lane == 0) red[wid] = s;
        __syncthreads();
        if (wid == 0) {
            float x = (lane < 8) ? red[lane] : 0.f;
            x = warpSum(x);
            if (lane == 0) red[0] = x;
        }
        __syncthreads();
        float inv = 1.0f / red[0];
        __syncthreads();

        // write E as bf16 hi/lo planes
        const size_t ebase = ((size_t)bh * NN + i) * NN;
        #pragma unroll
        for (int r = 0; r < 4; r++) {
            __nv_bfloat16 hi[4], lo[4];
            split_bf16(p[r*4+0], hi[0], lo[0]);
            split_bf16(p[r*4+1], hi[1], lo[1]);
            split_bf16(p[r*4+2], hi[2], lo[2]);
            split_bf16(p[r*4+3], hi[3], lo[3]);
            size_t off = ebase + (size_t)(tid + r * 256) * 4;
            *(uint2*)&g_Ebf[off]          = *(uint2*)hi;
            *(uint2*)&g_Ebf[EPLANE + off] = *(uint2*)lo;
        }
        if (tid == 0) g_il[(size_t)bh * NN + i] = inv;

        #pragma unroll
        for (int r = 0; r < 16; r++) macc[r] += p[r] * inv;
    }

    float* am = out_am + ((size_t)(b * NN) + i) * NN;
    #pragma unroll
    for (int r = 0; r < 4; r++) {
        float4 v = make_float4(macc[r*4+0] * 0.25f, macc[r*4+1] * 0.25f,
                               macc[r*4+2] * 0.25f, macc[r*4+3] * 0.25f);
        *(float4*)&am[(tid + r * 256) * 4] = v;
    }
}

// ---------------------------------------------------------------------------
// PV (mma.sync): AV[b,i,h*64+d] = inv_l[i] * sum_j E[bh,i,j] * V[b,j,h*64+d]
// tile 128(i) x 64(d), k-loop j in steps of 64, 3-pass hi/lo; pure-copy fills.
// grid: x=it(32), y=bh(8); 256 threads
// ---------------------------------------------------------------------------
#define LDV 72

__global__ __launch_bounds__(256) void pv_mma()
{
    extern __shared__ __nv_bfloat16 sm[];
    __nv_bfloat16* Ps = sm;                 // [128 i][LDQ]  (j: 64 hi | 64 lo)
    __nv_bfloat16* Vs = sm + 128 * LDQ;     // [128 j(hi|lo)][LDV]

    const int tid  = threadIdx.x;
    const int lane = tid & 31, warp = tid >> 5;
    const int wm = warp >> 1, wn = warp & 1;      // 4 x 2 warp grid (32x32)
    const int bh = blockIdx.y;
    const int b = bh >> 2, h = bh & 3;
    const int i0 = blockIdx.x * 128;

    float acc[2][4][4] = {};
    const uint32_t pbase = smem_u32(Ps);
    const uint32_t vbase = smem_u32(Vs);

    const size_t erow = ((size_t)bh * NN + i0) * NN;
    const size_t voff = (size_t)(b * NN) * HH + h * DH;

    for (int jt = 0; jt < NN; jt += 64) {
        __syncthreads();
        // E tile: plane(2) x row(128) x c(8) = 2048 uint4 chunks
        #pragma unroll
        for (int it = 0; it < 8; it++) {
            int f = tid + it * 256;
            int p = f >> 10;
            int r = (f >> 3) & 127;
            int c = f & 7;
            const __nv_bfloat16* src = g_Ebf + (size_t)p * EPLANE
                                     + erow + (size_t)r * NN + jt + c * 8;
            *(uint4*)(Ps + r * LDQ + p * 64 + c * 8) = *(const uint4*)src;
        }
        // V tile: plane(2) x jr(64) x c(8) = 1024 uint4 chunks
        #pragma unroll
        for (int it = 0; it < 4; it++) {
            int f  = tid + it * 256;
            int p  = f >> 9;
            int jr = (f >> 3) & 63;
            int c  = f & 7;
            const __nv_bfloat16* src = g_Vbf + (size_t)p * PLANE
                                     + voff + (size_t)(jt + jr) * HH + c * 8;
            *(uint4*)(Vs + (jr + p * 64) * LDV + c * 8) = *(const uint4*)src;
        }
        __syncthreads();

        #pragma unroll
        for (int pass = 0; pass < 3; pass++) {
            const int aOff = (pass == 1) ? 64 : 0;   // E lo
            const int bOff = (pass == 2) ? 64 : 0;   // V lo (row offset)
            #pragma unroll
            for (int ks = 0; ks < 4; ks++) {
                const int kc = ks * 16;
                uint32_t a[2][4];
                #pragma unroll
                for (int mt = 0; mt < 2; mt++) {
                    int r = wm * 32 + mt * 16 + (lane & 15);
                    int c = aOff + kc + ((lane >> 4) << 3);
                    ldsm_x4(pbase + (uint32_t)(r * LDQ + c) * 2,
                            a[mt][0], a[mt][1], a[mt][2], a[mt][3]);
                }
                uint32_t bf[4][2];
                #pragma unroll
                for (int hf = 0; hf < 2; hf++) {
                    int r = bOff + kc + (lane & 7) + ((lane & 8) ? 8 : 0);
                    int c = wn * 32 + hf * 16 + ((lane >> 4) << 3);
                    uint32_t r0, r1, r2, r3;
                    ldsm_x4_t(vbase + (uint32_t)(r * LDV + c) * 2, r0, r1, r2, r3);
                    bf[hf * 2 + 0][0] = r0; bf[hf * 2 + 0][1] = r1;
                    bf[hf * 2 + 1][0] = r2; bf[hf * 2 + 1][1] = r3;
                }
                #pragma unroll
                for (int mt = 0; mt < 2; mt++)
                    #pragma unroll
                    for (int nt = 0; nt < 4; nt++)
                        mma_bf16(acc[mt][nt], a[mt], bf[nt]);
            }
        }
    }

    const int g  = lane >> 2;
    const int t2 = (lane & 3) * 2;
    #pragma unroll
    for (int mt = 0; mt < 2; mt++) {
        const int r0 = i0 + wm * 32 + mt * 16 + g;
        const int r1 = r0 + 8;
        const float il0 = g_il[(size_t)bh * NN + r0];
        const float il1 = g_il[(size_t)bh * NN + r1];
        #pragma unroll
        for (int nt = 0; nt < 4; nt++) {
            const int d = wn * 32 + nt * 8 + t2;
            float* ac = acc[mt][nt];
            *(float2*)&g_AV[(size_t)(b * NN + r0) * HH + h * DH + d] =
                make_float2(ac[0] * il0, ac[1] * il0);
            *(float2*)&g_AV[(size_t)(b * NN + r1) * HH + h * DH + d] =
                make_float2(ac[2] * il1, ac[3] * il1);
        }
    }
}

// ---------------------------------------------------------------------------
// Launch
// inputs: 0:h 1:tau 2:adj_mask 3:Wq 4:bq 5:Wk 6:bk 7:Wv 8:bv 9:cw 10:cb 11:Wo 12:bo
// ---------------------------------------------------------------------------
extern "C" void kernel_launch(void* const* d_in, const int* in_sizes, int n_in,
                              void* d_out, int out_size)
{
    const float* h_in = (const float*)d_in[0];
    const float* tau  = (const float*)d_in[1];
    const int*   adj  = (const int*)  d_in[2];
    const float* Wq   = (const float*)d_in[3];
    const float* bq   = (const float*)d_in[4];
    const float* Wk   = (const float*)d_in[5];
    const float* bk   = (const float*)d_in[6];
    const float* Wv   = (const float*)d_in[7];
    const float* bv   = (const float*)d_in[8];
    const float* cw   = (const float*)d_in[9];
    const float* cb   = (const float*)d_in[10];
    const float* Wo   = (const float*)d_in[11];
    const float* bo   = (const float*)d_in[12];

    float* out_h  = (float*)d_out;
    float* out_am = out_h + (size_t)MTOT * HH;

    void *pQ, *pK, *pV, *pAV;
    cudaGetSymbolAddress(&pQ,  g_Q);
    cudaGetSymbolAddress(&pK,  g_K);
    cudaGetSymbolAddress(&pV,  g_V);
    cudaGetSymbolAddress(&pAV, g_AV);

    const int smem_scores = 2 * 128 * LDQ * 2;             // 69632 B
    const int smem_pv     = (128 * LDQ + 128 * LDV) * 2;   // 53248 B
    cudaFuncSetAttribute(scores_mma, cudaFuncAttributeMaxDynamicSharedMemorySize, smem_scores);
    cudaFuncSetAttribute(pv_mma,     cudaFuncAttributeMaxDynamicSharedMemorySize, smem_pv);

    dim3 gProj(MTOT / 64, HH / 64);
    gemm_xwt<<<gProj, 256>>>(h_in, Wq, bq, (float*)pQ);
    gemm_xwt<<<gProj, 256>>>(h_in, Wk, bk, (float*)pK);
    gemm_xwt<<<gProj, 256>>>(h_in, Wv, bv, (float*)pV);

    convert_qkv_kernel<<<dim3(PLANE / 4 / 256, 3), 256>>>();

    scores_mma<<<dim3(BB * NHEADS, NN / 128, NN / 128), 256, smem_scores>>>(tau, adj, cw, cb);

    softmax_kernel<<<BB * NN, 256>>>(out_am);

    pv_mma<<<dim3(NN / 128, BB * NHEADS), 256, smem_pv>>>();

    gemm_xwt<<<gProj, 256>>>((const float*)pAV, Wo, bo, out_h);
}